// round 12
// baseline (speedup 1.0000x reference)
#include <cuda_runtime.h>

// ---------------------------------------------------------------------------
// TrackCrop: input [32, 512, 512, 3] f32.
// Two kernels (fixed ~3.6us/replay overhead is kernel-count independent):
//  reduce: grid (64,32) x 128 thr, 8 rows/block, ~6.1 TB/s (near LTS cap).
//          Packed accumulator: one predicated IADD per element carries
//          sx (low 20b) + cnt (high). Ticket finalizer publishes crop
//          origin; scratch self-resets for graph replay.
//  crop:   same proven body as R11, but grid (64,32), 4 rows/block ->
//          2x occupancy (crop was latency-bound at occ 50%).
// ---------------------------------------------------------------------------

#define NBATCH 32
#define SY 512
#define SX 512
#define NC 3
#define ROW_FLOATS (SX * NC)        // 1536
#define ROW_F4 (ROW_FLOATS / 4)     // 384
#define CROP 256
#define OUT_ROW_FLOATS (CROP * NC)  // 768

#define RB 8                        // rows per reduce block
#define RBLOCKS_PER_BATCH (SY / RB) // 64

#define CR 4                        // rows per crop block
#define CBLOCKS_PER_BATCH (CROP / CR) // 64

#define CNT_ONE (1 << 20)           // cnt above bit 20; sx below
#define SX_MASK (CNT_ONE - 1)

__device__ int  g_cnt[NBATCH];   // zero at load; returned to 0 every run
__device__ int  g_sx[NBATCH];
__device__ int  g_sy[NBATCH];
__device__ int  g_tick[NBATCH];
__device__ int2 g_HW[NBATCH];    // (H, W) crop origin per batch

__global__ __launch_bounds__(128) void reduce_kernel(const float* __restrict__ in) {
    const int t  = threadIdx.x;             // 0..127
    const int b  = blockIdx.y;              // 0..31
    const int y0 = blockIdx.x * RB;         // 0,8,...,504

    // Per-lane packed weights: x-coordinate + CNT_ONE, hoisted out of loop.
    int w[12];
    #pragma unroll
    for (int i = 0; i < 3; i++) {
        const int j = 4 * (t + i * 128);    // float index within row
        #pragma unroll
        for (int k = 0; k < 4; k++)
            w[i * 4 + k] = (j + k) / 3 + CNT_ONE;
    }

    const float4* __restrict__ base =
        (const float4*)(in + ((size_t)b * SY + y0) * ROW_FLOATS);

    int accT = 0;   // packed: sx [0,20), cnt [20,..)  (cnt<=96, sx<=49K: safe)
    int sy   = 0;
    #pragma unroll
    for (int r = 0; r < RB; r++) {
        const float4* __restrict__ row = base + (size_t)r * ROW_F4;
        const float4 a = row[t];
        const float4 c = row[t + 128];
        const float4 d = row[t + 256];

        int acc = 0;
        if (a.x != 0.0f) acc += w[0];
        if (a.y != 0.0f) acc += w[1];
        if (a.z != 0.0f) acc += w[2];
        if (a.w != 0.0f) acc += w[3];
        if (c.x != 0.0f) acc += w[4];
        if (c.y != 0.0f) acc += w[5];
        if (c.z != 0.0f) acc += w[6];
        if (c.w != 0.0f) acc += w[7];
        if (d.x != 0.0f) acc += w[8];
        if (d.y != 0.0f) acc += w[9];
        if (d.z != 0.0f) acc += w[10];
        if (d.w != 0.0f) acc += w[11];

        accT += acc;
        sy   += (y0 + r) * (acc >> 20);     // row count
    }

    int cnt = accT >> 20;
    int sx  = accT & SX_MASK;

    // warp reduce
    #pragma unroll
    for (int o = 16; o > 0; o >>= 1) {
        cnt += __shfl_down_sync(0xFFFFFFFFu, cnt, o);
        sx  += __shfl_down_sync(0xFFFFFFFFu, sx,  o);
        sy  += __shfl_down_sync(0xFFFFFFFFu, sy,  o);
    }

    __shared__ int s_cnt, s_sx, s_sy;
    if (t == 0) { s_cnt = 0; s_sx = 0; s_sy = 0; }
    __syncthreads();
    if ((t & 31) == 0) {
        atomicAdd(&s_cnt, cnt);
        atomicAdd(&s_sx,  sx);
        atomicAdd(&s_sy,  sy);
    }
    __syncthreads();

    if (t == 0) {
        atomicAdd(&g_cnt[b], s_cnt);
        atomicAdd(&g_sx[b],  s_sx);
        atomicAdd(&g_sy[b],  s_sy);
        __threadfence();
        if (atomicAdd(&g_tick[b], 1) == RBLOCKS_PER_BATCH - 1) {
            // Last block for this batch: read+reset (scratch back to 0 for
            // the next graph replay), publish crop origin.
            const int c  = atomicExch(&g_cnt[b], 0);
            const int xs = atomicExch(&g_sx[b],  0);
            const int ys = atomicExch(&g_sy[b],  0);
            atomicExch(&g_tick[b], 0);
            // Reference numerics: int32->f32 RN, IEEE f32 divide, trunc cast.
            const float fc = __int2float_rn(c);
            const int xcm = (int)__fdiv_rn(__int2float_rn(xs), fc);
            const int ycm = (int)__fdiv_rn(__int2float_rn(ys), fc);
            int2 hw;
            hw.x = min(max(ycm - CROP / 2, 0), SY - 1 - CROP);  // H
            hw.y = min(max(xcm - CROP / 2, 0), SX - 1 - CROP);  // W
            g_HW[b] = hw;
        }
    }
}

// Crop: 192 threads, 4 output rows per block (2048 blocks -> ~2x occupancy
// vs the 8-row variant). Scalar loads (source only 4B-aligned since W*3 is
// arbitrary), aligned float4 stores.
__global__ __launch_bounds__(192) void crop_kernel(const float* __restrict__ in,
                                                   float* __restrict__ out) {
    const int t  = threadIdx.x;          // 0..191
    const int b  = blockIdx.y;           // batch
    const int r0 = blockIdx.x * CR;      // first output row of this block

    const int2 hw = g_HW[b];             // (H, W)

    const float* __restrict__ srcb =
        in + (size_t)b * (SY * SX * NC)
           + ((size_t)(hw.x + r0) * SX + hw.y) * NC
           + 4 * t;
    float4* __restrict__ dstb =
        (float4*)(out + ((size_t)b * CROP + r0) * OUT_ROW_FLOATS) + t;

    #pragma unroll
    for (int r = 0; r < CR; r++) {
        const float* __restrict__ src = srcb + (size_t)r * ROW_FLOATS;
        float4 v;
        v.x = src[0];
        v.y = src[1];
        v.z = src[2];
        v.w = src[3];
        dstb[(size_t)r * (OUT_ROW_FLOATS / 4)] = v;
    }
}

extern "C" void kernel_launch(void* const* d_in, const int* in_sizes, int n_in,
                              void* d_out, int out_size) {
    const float* in = (const float*)d_in[0];
    float* out = (float*)d_out;

    reduce_kernel<<<dim3(RBLOCKS_PER_BATCH, NBATCH), 128>>>(in);
    crop_kernel<<<dim3(CBLOCKS_PER_BATCH, NBATCH), 192>>>(in, out);
}

// round 13
// speedup vs baseline: 1.0412x; 1.0412x over previous
#include <cuda_runtime.h>

// ---------------------------------------------------------------------------
// TrackCrop: input [32, 512, 512, 3] f32.
// Two kernels:
//  reduce: grid (64,32) x 192 thr, 8 rows/block, 2 float4/thread/row.
//          ~28 regs -> ~94% occupancy (128-thr version was reg-limited to
//          75%). Packed accumulator: one predicated IADD per element carries
//          sx (low 20b) + cnt (high). Ticket finalizer publishes crop origin;
//          scratch self-resets for graph replay.
//  crop:   proven body (invariant ~10.5us across occ/MLP/pattern), stores
//          with __stcs (output never re-read; keep L2 for input).
// ---------------------------------------------------------------------------

#define NBATCH 32
#define SY 512
#define SX 512
#define NC 3
#define ROW_FLOATS (SX * NC)        // 1536
#define ROW_F4 (ROW_FLOATS / 4)     // 384
#define CROP 256
#define OUT_ROW_FLOATS (CROP * NC)  // 768

#define RT 192                      // reduce threads (= ROW_F4 / 2)
#define RB 8                        // rows per reduce block
#define RBLOCKS_PER_BATCH (SY / RB) // 64

#define CR 4                        // rows per crop block
#define CBLOCKS_PER_BATCH (CROP / CR) // 64

#define CNT_ONE (1 << 20)           // cnt above bit 20; sx below
#define SX_MASK (CNT_ONE - 1)

__device__ int  g_cnt[NBATCH];   // zero at load; returned to 0 every run
__device__ int  g_sx[NBATCH];
__device__ int  g_sy[NBATCH];
__device__ int  g_tick[NBATCH];
__device__ int2 g_HW[NBATCH];    // (H, W) crop origin per batch

__global__ __launch_bounds__(RT) void reduce_kernel(const float* __restrict__ in) {
    const int t  = threadIdx.x;             // 0..191
    const int b  = blockIdx.y;              // 0..31
    const int y0 = blockIdx.x * RB;         // 0,8,...,504

    // This thread's 8 float lanes: j0 = 4t..4t+3 and j1 = 4t+768..4t+771.
    // Packed weight = x + CNT_ONE, hoisted out of the loop.
    int w[8];
    {
        const int j0 = 4 * t;
        const int j1 = 4 * (t + RT);
        #pragma unroll
        for (int k = 0; k < 4; k++) {
            w[k]     = (j0 + k) / 3 + CNT_ONE;
            w[4 + k] = (j1 + k) / 3 + CNT_ONE;
        }
    }

    const float4* __restrict__ base =
        (const float4*)(in + ((size_t)b * SY + y0) * ROW_FLOATS);

    int accT = 0;   // packed: sx [0,20), cnt [20,..)  (cnt<=64, sx<=33K: safe)
    int sy   = 0;
    #pragma unroll
    for (int r = 0; r < RB; r++) {
        const float4* __restrict__ row = base + (size_t)r * ROW_F4;
        const float4 a = row[t];
        const float4 d = row[t + RT];

        int acc = 0;
        if (a.x != 0.0f) acc += w[0];
        if (a.y != 0.0f) acc += w[1];
        if (a.z != 0.0f) acc += w[2];
        if (a.w != 0.0f) acc += w[3];
        if (d.x != 0.0f) acc += w[4];
        if (d.y != 0.0f) acc += w[5];
        if (d.z != 0.0f) acc += w[6];
        if (d.w != 0.0f) acc += w[7];

        accT += acc;
        sy   += (y0 + r) * (acc >> 20);     // row count
    }

    int cnt = accT >> 20;
    int sx  = accT & SX_MASK;

    // warp reduce
    #pragma unroll
    for (int o = 16; o > 0; o >>= 1) {
        cnt += __shfl_down_sync(0xFFFFFFFFu, cnt, o);
        sx  += __shfl_down_sync(0xFFFFFFFFu, sx,  o);
        sy  += __shfl_down_sync(0xFFFFFFFFu, sy,  o);
    }

    __shared__ int s_cnt, s_sx, s_sy;
    if (t == 0) { s_cnt = 0; s_sx = 0; s_sy = 0; }
    __syncthreads();
    if ((t & 31) == 0) {
        atomicAdd(&s_cnt, cnt);
        atomicAdd(&s_sx,  sx);
        atomicAdd(&s_sy,  sy);
    }
    __syncthreads();

    if (t == 0) {
        atomicAdd(&g_cnt[b], s_cnt);
        atomicAdd(&g_sx[b],  s_sx);
        atomicAdd(&g_sy[b],  s_sy);
        __threadfence();
        if (atomicAdd(&g_tick[b], 1) == RBLOCKS_PER_BATCH - 1) {
            // Last block for this batch: read+reset (scratch back to 0 for
            // the next graph replay), publish crop origin.
            const int c  = atomicExch(&g_cnt[b], 0);
            const int xs = atomicExch(&g_sx[b],  0);
            const int ys = atomicExch(&g_sy[b],  0);
            atomicExch(&g_tick[b], 0);
            // Reference numerics: int32->f32 RN, IEEE f32 divide, trunc cast.
            const float fc = __int2float_rn(c);
            const int xcm = (int)__fdiv_rn(__int2float_rn(xs), fc);
            const int ycm = (int)__fdiv_rn(__int2float_rn(ys), fc);
            int2 hw;
            hw.x = min(max(ycm - CROP / 2, 0), SY - 1 - CROP);  // H
            hw.y = min(max(xcm - CROP / 2, 0), SX - 1 - CROP);  // W
            g_HW[b] = hw;
        }
    }
}

// Crop: 192 threads, 4 output rows per block. Scalar loads (source only
// 4B-aligned since W*3 is arbitrary), aligned float4 streaming stores.
__global__ __launch_bounds__(192) void crop_kernel(const float* __restrict__ in,
                                                   float* __restrict__ out) {
    const int t  = threadIdx.x;          // 0..191
    const int b  = blockIdx.y;           // batch
    const int r0 = blockIdx.x * CR;      // first output row of this block

    const int2 hw = g_HW[b];             // (H, W)

    const float* __restrict__ srcb =
        in + (size_t)b * (SY * SX * NC)
           + ((size_t)(hw.x + r0) * SX + hw.y) * NC
           + 4 * t;
    float4* __restrict__ dstb =
        (float4*)(out + ((size_t)b * CROP + r0) * OUT_ROW_FLOATS) + t;

    #pragma unroll
    for (int r = 0; r < CR; r++) {
        const float* __restrict__ src = srcb + (size_t)r * ROW_FLOATS;
        float4 v;
        v.x = src[0];
        v.y = src[1];
        v.z = src[2];
        v.w = src[3];
        __stcs(dstb + (size_t)r * (OUT_ROW_FLOATS / 4), v);
    }
}

extern "C" void kernel_launch(void* const* d_in, const int* in_sizes, int n_in,
                              void* d_out, int out_size) {
    const float* in = (const float*)d_in[0];
    float* out = (float*)d_out;

    reduce_kernel<<<dim3(RBLOCKS_PER_BATCH, NBATCH), RT>>>(in);
    crop_kernel<<<dim3(CBLOCKS_PER_BATCH, NBATCH), 192>>>(in, out);
}

// round 14
// speedup vs baseline: 1.0561x; 1.0143x over previous
#include <cuda_runtime.h>

// ---------------------------------------------------------------------------
// TrackCrop: input [32, 512, 512, 3] f32.
// Two kernels:
//  reduce: grid (32,32) x 192 thr, 16 rows/block, 2 float4/thread/row.
//          ~94% occupancy, 16-deep unrolled load loop, half the block
//          overhead of the RB=8 variant. Packed accumulator: one predicated
//          IADD per element carries sx (low 20b) + cnt (high). Ticket
//          finalizer publishes crop origin; scratch self-resets for replay.
//  crop:   frozen proven body (~10.5us floor across 5 variants): 192 thr,
//          4 rows/block, scalar loads + float4 streaming stores.
// ---------------------------------------------------------------------------

#define NBATCH 32
#define SY 512
#define SX 512
#define NC 3
#define ROW_FLOATS (SX * NC)        // 1536
#define ROW_F4 (ROW_FLOATS / 4)     // 384
#define CROP 256
#define OUT_ROW_FLOATS (CROP * NC)  // 768

#define RT 192                      // reduce threads (= ROW_F4 / 2)
#define RB 16                       // rows per reduce block
#define RBLOCKS_PER_BATCH (SY / RB) // 32

#define CR 4                        // rows per crop block
#define CBLOCKS_PER_BATCH (CROP / CR) // 64

#define CNT_ONE (1 << 20)           // cnt above bit 20; sx below
#define SX_MASK (CNT_ONE - 1)

__device__ int  g_cnt[NBATCH];   // zero at load; returned to 0 every run
__device__ int  g_sx[NBATCH];
__device__ int  g_sy[NBATCH];
__device__ int  g_tick[NBATCH];
__device__ int2 g_HW[NBATCH];    // (H, W) crop origin per batch

__global__ __launch_bounds__(RT) void reduce_kernel(const float* __restrict__ in) {
    const int t  = threadIdx.x;             // 0..191
    const int b  = blockIdx.y;              // 0..31
    const int y0 = blockIdx.x * RB;         // 0,16,...,496

    // This thread's 8 float lanes: j0 = 4t..4t+3 and j1 = 4t+768..4t+771.
    // Packed weight = x + CNT_ONE, hoisted out of the loop.
    int w[8];
    {
        const int j0 = 4 * t;
        const int j1 = 4 * (t + RT);
        #pragma unroll
        for (int k = 0; k < 4; k++) {
            w[k]     = (j0 + k) / 3 + CNT_ONE;
            w[4 + k] = (j1 + k) / 3 + CNT_ONE;
        }
    }

    const float4* __restrict__ base =
        (const float4*)(in + ((size_t)b * SY + y0) * ROW_FLOATS);

    int accT = 0;   // packed: sx [0,20), cnt [20,..)  (cnt<=128, sx<=65K: safe)
    int sy   = 0;
    #pragma unroll
    for (int r = 0; r < RB; r++) {
        const float4* __restrict__ row = base + (size_t)r * ROW_F4;
        const float4 a = row[t];
        const float4 d = row[t + RT];

        int acc = 0;
        if (a.x != 0.0f) acc += w[0];
        if (a.y != 0.0f) acc += w[1];
        if (a.z != 0.0f) acc += w[2];
        if (a.w != 0.0f) acc += w[3];
        if (d.x != 0.0f) acc += w[4];
        if (d.y != 0.0f) acc += w[5];
        if (d.z != 0.0f) acc += w[6];
        if (d.w != 0.0f) acc += w[7];

        accT += acc;
        sy   += (y0 + r) * (acc >> 20);     // row count
    }

    int cnt = accT >> 20;
    int sx  = accT & SX_MASK;

    // warp reduce
    #pragma unroll
    for (int o = 16; o > 0; o >>= 1) {
        cnt += __shfl_down_sync(0xFFFFFFFFu, cnt, o);
        sx  += __shfl_down_sync(0xFFFFFFFFu, sx,  o);
        sy  += __shfl_down_sync(0xFFFFFFFFu, sy,  o);
    }

    __shared__ int s_cnt, s_sx, s_sy;
    if (t == 0) { s_cnt = 0; s_sx = 0; s_sy = 0; }
    __syncthreads();
    if ((t & 31) == 0) {
        atomicAdd(&s_cnt, cnt);
        atomicAdd(&s_sx,  sx);
        atomicAdd(&s_sy,  sy);
    }
    __syncthreads();

    if (t == 0) {
        atomicAdd(&g_cnt[b], s_cnt);
        atomicAdd(&g_sx[b],  s_sx);
        atomicAdd(&g_sy[b],  s_sy);
        __threadfence();
        if (atomicAdd(&g_tick[b], 1) == RBLOCKS_PER_BATCH - 1) {
            // Last block for this batch: read+reset (scratch back to 0 for
            // the next graph replay), publish crop origin.
            const int c  = atomicExch(&g_cnt[b], 0);
            const int xs = atomicExch(&g_sx[b],  0);
            const int ys = atomicExch(&g_sy[b],  0);
            atomicExch(&g_tick[b], 0);
            // Reference numerics: int32->f32 RN, IEEE f32 divide, trunc cast.
            const float fc = __int2float_rn(c);
            const int xcm = (int)__fdiv_rn(__int2float_rn(xs), fc);
            const int ycm = (int)__fdiv_rn(__int2float_rn(ys), fc);
            int2 hw;
            hw.x = min(max(ycm - CROP / 2, 0), SY - 1 - CROP);  // H
            hw.y = min(max(xcm - CROP / 2, 0), SX - 1 - CROP);  // W
            g_HW[b] = hw;
        }
    }
}

// Crop (frozen): 192 threads, 4 output rows per block. Scalar loads (source
// only 4B-aligned since W*3 is arbitrary), aligned float4 streaming stores.
__global__ __launch_bounds__(192) void crop_kernel(const float* __restrict__ in,
                                                   float* __restrict__ out) {
    const int t  = threadIdx.x;          // 0..191
    const int b  = blockIdx.y;           // batch
    const int r0 = blockIdx.x * CR;      // first output row of this block

    const int2 hw = g_HW[b];             // (H, W)

    const float* __restrict__ srcb =
        in + (size_t)b * (SY * SX * NC)
           + ((size_t)(hw.x + r0) * SX + hw.y) * NC
           + 4 * t;
    float4* __restrict__ dstb =
        (float4*)(out + ((size_t)b * CROP + r0) * OUT_ROW_FLOATS) + t;

    #pragma unroll
    for (int r = 0; r < CR; r++) {
        const float* __restrict__ src = srcb + (size_t)r * ROW_FLOATS;
        float4 v;
        v.x = src[0];
        v.y = src[1];
        v.z = src[2];
        v.w = src[3];
        __stcs(dstb + (size_t)r * (OUT_ROW_FLOATS / 4), v);
    }
}

extern "C" void kernel_launch(void* const* d_in, const int* in_sizes, int n_in,
                              void* d_out, int out_size) {
    const float* in = (const float*)d_in[0];
    float* out = (float*)d_out;

    reduce_kernel<<<dim3(RBLOCKS_PER_BATCH, NBATCH), RT>>>(in);
    crop_kernel<<<dim3(CBLOCKS_PER_BATCH, NBATCH), 192>>>(in, out);
}